// round 8
// baseline (speedup 1.0000x reference)
#include <cuda_runtime.h>
#include <math.h>

// Problem dims
#define BB 64
#define TT 256
#define ZZ 128
#define HH 512
#define FF 64
#define MROWS (BB*TT)      // 16384
#define G4H   (4*HH)       // 2048
#define LSTM_BLOCKS (HH/4) // 128

// ------------------------------ scratch buffers ------------------------------
__device__ float d_xk[MROWS * G4H];     // 134 MB  gate pre-activations
__device__ float d_seqA[MROWS * HH];
__device__ float d_seqB[MROWS * HH];
__device__ float d_res[MROWS * HH];
__device__ float d_W0eff[ZZ * G4H];
__device__ float d_b0eff[G4H];
__device__ float d_hT[2 * HH * BB];     // double-buffered h, [buf][hidden][batch]
__device__ unsigned g_grp[8];           // hierarchical barrier: 8 groups of 16
__device__ unsigned g_root;
__device__ unsigned g_gen;

__device__ __forceinline__ float sigf(float x) { return 1.f / (1.f + expf(-x)); }

// packed f32x2 helpers
#define FMA2(c, a, b) \
    asm("fma.rn.f32x2 %0, %2, %3, %1;" : "=l"(c) : "l"(c), "l"(a), "l"(b))
#define ADD2PK(d, a, b) \
    asm("add.rn.f32x2 %0, %1, %2;" : "=l"(d) : "l"(a), "l"(b))
#define PACKDUP(d, f) \
    asm("mov.b64 %0, {%1, %1};" : "=l"(d) : "r"(__float_as_uint(f)))

__device__ __forceinline__ float f2lo(unsigned long long v) {
    return __uint_as_float((unsigned)v);
}
__device__ __forceinline__ float f2hi(unsigned long long v) {
    return __uint_as_float((unsigned)(v >> 32));
}

// ------------------------------ hierarchical grid barrier --------------------
__device__ __forceinline__ void grid_barrier(int grp) {
    __syncthreads();
    if (threadIdx.x == 0) {
        __threadfence();
        unsigned my = *(volatile unsigned*)&g_gen;
        if ((atomicAdd(&g_grp[grp], 1u) & 15u) == 15u) {
            if ((atomicAdd(&g_root, 1u) & 7u) == 7u) {
                atomicAdd(&g_gen, 1u);
            }
        }
        while (*(volatile unsigned*)&g_gen == my) {}
        __threadfence();
    }
    __syncthreads();
}

// ------------------------------ bias fold: b0eff = bp@K0 + b0 ----------------
__global__ void bias_fold_kernel(const float* __restrict__ bp,
                                 const float* __restrict__ K0,
                                 const float* __restrict__ b0) {
    __shared__ float red[8][32];
    const int c = threadIdx.x & 31, s = threadIdx.x >> 5;
    const int j = blockIdx.x * 32 + c;
    float acc = 0.f;
    for (int k = s * 128; k < s * 128 + 128; ++k)
        acc += bp[k] * K0[(size_t)k * G4H + j];
    red[s][c] = acc;
    __syncthreads();
    if (s == 0) {
        float t = 0.f;
#pragma unroll
        for (int r = 0; r < 8; ++r) t += red[r][c];
        d_b0eff[j] = t + b0[j];
    }
}

// ------------------------------ SGEMM 128x128x16, 8x8/thread, f32x2 ----------
// AMAP: 0 identity row, 1 (m=(t,b) -> source row b*T+t)
// ACT : 0 none, 1 relu
// ADD2A: A := A + A2 (identity-mapped rows)
// HASB: add bias[n]
template<int AMAP, int ACT, int ADD2A, int HASB>
__global__ __launch_bounds__(256, 2)
void sgemm128(const float* __restrict__ A, const float* __restrict__ A2,
              const float* __restrict__ Bm, const float* __restrict__ bias,
              float* __restrict__ C, int M, int N, int K) {
    __shared__ float As[16][128];
    __shared__ float Bs[16][128];
    const int tid = threadIdx.x;
    const int n0 = blockIdx.x * 128, m0 = blockIdx.y * 128;
    const int r = tid >> 2, kq = (tid & 3) * 4;
    const int kb = tid >> 5, n4 = (tid & 31) * 4;
    const int tm = tid >> 4, tn = tid & 15;

    unsigned long long acc2[8][4];
#pragma unroll
    for (int i = 0; i < 8; ++i)
#pragma unroll
        for (int j = 0; j < 4; ++j) acc2[i][j] = 0ULL;

    for (int k0 = 0; k0 < K; k0 += 16) {
#pragma unroll
        for (int h = 0; h < 2; ++h) {   // A tile, transposed store
            int rr = r + h * 64;
            int m = m0 + rr;
            int arow = (AMAP == 1) ? ((m & 63) * TT + (m >> 6)) : m;
            float4 av = *(const float4*)(A + (size_t)arow * K + k0 + kq);
            if (ADD2A) {
                float4 a2 = *(const float4*)(A2 + (size_t)m * K + k0 + kq);
                av.x += a2.x; av.y += a2.y; av.z += a2.z; av.w += a2.w;
            }
            As[kq + 0][rr] = av.x;
            As[kq + 1][rr] = av.y;
            As[kq + 2][rr] = av.z;
            As[kq + 3][rr] = av.w;
        }
#pragma unroll
        for (int h = 0; h < 2; ++h) {   // B tile
            int kk = kb + h * 8;
            *(float4*)&Bs[kk][n4] =
                *(const float4*)(Bm + (size_t)(k0 + kk) * N + n0 + n4);
        }
        __syncthreads();
#pragma unroll
        for (int k = 0; k < 16; ++k) {
            float4 a0 = *(const float4*)&As[k][tm * 8];
            float4 a1 = *(const float4*)&As[k][tm * 8 + 4];
            const ulonglong2* bp2 = (const ulonglong2*)&Bs[k][tn * 8];
            ulonglong2 bA = bp2[0];
            ulonglong2 bB = bp2[1];
            float ar[8] = {a0.x, a0.y, a0.z, a0.w, a1.x, a1.y, a1.z, a1.w};
#pragma unroll
            for (int i = 0; i < 8; ++i) {
                unsigned long long ad;
                PACKDUP(ad, ar[i]);
                FMA2(acc2[i][0], ad, bA.x);
                FMA2(acc2[i][1], ad, bA.y);
                FMA2(acc2[i][2], ad, bB.x);
                FMA2(acc2[i][3], ad, bB.y);
            }
        }
        __syncthreads();
    }

#pragma unroll
    for (int i = 0; i < 8; ++i) {
        int m = m0 + tm * 8 + i;
        size_t ro = (size_t)m * N;
        float vals[8];
#pragma unroll
        for (int j2 = 0; j2 < 4; ++j2) {
            vals[2 * j2]     = f2lo(acc2[i][j2]);
            vals[2 * j2 + 1] = f2hi(acc2[i][j2]);
        }
#pragma unroll
        for (int j = 0; j < 8; ++j) {
            int n = n0 + tn * 8 + j;
            float t = vals[j];
            if (HASB) t += bias[n];
            if (ACT == 1) t = fmaxf(t, 0.f);
            vals[j] = t;
        }
        *(float4*)(C + ro + n0 + tn * 8)     = make_float4(vals[0], vals[1], vals[2], vals[3]);
        *(float4*)(C + ro + n0 + tn * 8 + 4) = make_float4(vals[4], vals[5], vals[6], vals[7]);
    }
}

// ------------------------------ SGEMM 64x64x16 (small shapes) ----------------
// OMAP: 0 identity, 1 (t,b)->(b,t) output rows ; ACT: 0 none, 2 tanh
template<int ACT, int OMAP, int HASB>
__global__ __launch_bounds__(256)
void sgemm64(const float* __restrict__ A, const float* __restrict__ Bm,
             const float* __restrict__ bias, float* __restrict__ C,
             int M, int N, int K) {
    __shared__ float As[16][64];
    __shared__ float Bs[16][64];
    const int tid = threadIdx.x;
    const int tx = tid & 15, ty = tid >> 4;
    const int n0 = blockIdx.x * 64, m0 = blockIdx.y * 64;

    float acc[4][4];
#pragma unroll
    for (int i = 0; i < 4; ++i)
#pragma unroll
        for (int j = 0; j < 4; ++j) acc[i][j] = 0.f;

    const int arowl = tid >> 2;
    const int kq = (tid & 3) * 4;
    const int krow = tid >> 4;
    const int nq = (tid & 15) * 4;

    for (int k0 = 0; k0 < K; k0 += 16) {
        {
            int m = m0 + arowl;
            float4 av = *(const float4*)(A + (size_t)m * K + k0 + kq);
            As[kq + 0][arowl] = av.x;
            As[kq + 1][arowl] = av.y;
            As[kq + 2][arowl] = av.z;
            As[kq + 3][arowl] = av.w;
        }
        *(float4*)&Bs[krow][nq] =
            *(const float4*)(Bm + (size_t)(k0 + krow) * N + n0 + nq);
        __syncthreads();
#pragma unroll
        for (int k = 0; k < 16; ++k) {
            float4 a = *(const float4*)&As[k][ty * 4];
            float4 b = *(const float4*)&Bs[k][tx * 4];
            float ar[4] = {a.x, a.y, a.z, a.w};
            float br[4] = {b.x, b.y, b.z, b.w};
#pragma unroll
            for (int i = 0; i < 4; ++i)
#pragma unroll
                for (int j = 0; j < 4; ++j) acc[i][j] += ar[i] * br[j];
        }
        __syncthreads();
    }

#pragma unroll
    for (int i = 0; i < 4; ++i) {
        int m = m0 + ty * 4 + i;
        size_t ro = (OMAP == 1) ? (size_t)((m & 63) * TT + (m >> 6)) * N
                                : (size_t)m * N;
        float4 v;
        float* vp = (float*)&v;
#pragma unroll
        for (int j = 0; j < 4; ++j) {
            int n = n0 + tx * 4 + j;
            float t = acc[i][j];
            if (HASB) t += bias[n];
            if (ACT == 2) t = tanhf(t);
            vp[j] = t;
        }
        *(float4*)(C + ro + n0 + tx * 4) = v;
    }
}

// ------------------------------ LSTM recurrence v4 (unchanged) ---------------
#define LSTM_SMEM_FLOATS (16384 + 16384 + 1024 + 256)
__global__ __launch_bounds__(512)
void lstm_kernel(const float* __restrict__ xk, const float* __restrict__ R,
                 float* __restrict__ hseq) {
    extern __shared__ float smem[];
    float* pw   = smem;                  // 16384 floats: per-warp partials
    float* Rdup = smem + 16384;          // 16384 floats: duplicated R slice
    float* gsmT = smem + 32768;          // 1024 floats [j][b]
    float* csm  = gsmT + 1024;           // 256 floats

    const int tid = threadIdx.x;
    const int cb  = blockIdx.x * 4;
    const int grp = blockIdx.x >> 4;

    for (int idx = tid; idx < HH * 16; idx += 512) {
        int k = idx >> 4, j = idx & 15;
        float v = R[(size_t)k * G4H + (j >> 2) * HH + cb + (j & 3)];
        Rdup[k * 32 + j * 2]     = v;
        Rdup[k * 32 + j * 2 + 1] = v;
    }
    if (tid < 256)
        __stcg(&d_hT[(cb + (tid >> 6)) * BB + (tid & 63)], 0.f);
    if (tid < 256) csm[tid] = 0.f;
    grid_barrier(grp);

    const int lane = tid & 31;
    const int wi   = tid >> 5;       // warp: k-range [32wi, 32wi+32)
    const int jg   = lane >> 4;      // col group (8 cols each)
    const int bg   = lane & 15;      // batch quad

    const ulonglong2* RdU2 = (const ulonglong2*)Rdup;

    const int rj   = tid >> 5;       // gate col 0..15
    const int rbp  = tid & 31;       // batch pair 0..31
    const int rb0  = rbp * 2;
    const int rcol = (rj >> 2) * HH + cb + (rj & 3);

    for (int t = 0; t < TT; ++t) {
        const float* hcur = d_hT + (t & 1) * (HH * BB);
        float* hnxt       = d_hT + ((t + 1) & 1) * (HH * BB);
        const float* xkt  = xk + (size_t)t * BB * G4H;

        float xpre0 = __ldg(xkt + (size_t)rb0 * G4H + rcol);
        float xpre1 = __ldg(xkt + (size_t)(rb0 + 1) * G4H + rcol);

        unsigned long long acc2[8][2];
#pragma unroll
        for (int i = 0; i < 8; ++i) { acc2[i][0] = 0ULL; acc2[i][1] = 0ULL; }

        const double2* hp = (const double2*)(hcur + wi * 32 * 64 + bg * 4);
        const ulonglong2* rp = RdU2 + wi * 32 * 8 + jg * 4;
#pragma unroll 8
        for (int kk = 0; kk < 32; ++kk) {
            double2 hd = __ldcg(hp + kk * 16);
            unsigned long long h01 = __double_as_longlong(hd.x);
            unsigned long long h23 = __double_as_longlong(hd.y);
            const ulonglong2* rr = rp + kk * 8;
#pragma unroll
            for (int i = 0; i < 4; ++i) {
                ulonglong2 rv = rr[i];
                FMA2(acc2[2 * i][0],     rv.x, h01);
                FMA2(acc2[2 * i][1],     rv.x, h23);
                FMA2(acc2[2 * i + 1][0], rv.y, h01);
                FMA2(acc2[2 * i + 1][1], rv.y, h23);
            }
        }

        {
            float4* pw4 = (float4*)pw;
#pragma unroll
            for (int ji = 0; ji < 8; ++ji) {
                int j = jg * 8 + ji;
                float4 v;
                v.x = f2lo(acc2[ji][0]); v.y = f2hi(acc2[ji][0]);
                v.z = f2lo(acc2[ji][1]); v.w = f2hi(acc2[ji][1]);
                pw4[wi * 256 + j * 16 + bg] = v;
            }
        }
        __syncthreads();

        {
            const unsigned long long* pw2 = (const unsigned long long*)pw;
            unsigned long long a = pw2[rj * 32 + rbp];
#pragma unroll
            for (int w2 = 1; w2 < 16; ++w2) {
                unsigned long long o = pw2[w2 * 512 + rj * 32 + rbp];
                ADD2PK(a, a, o);
            }
            float g0 = f2lo(a) + xpre0;
            float g1 = f2hi(a) + xpre1;
            ((float2*)gsmT)[rj * 32 + rbp] = make_float2(g0, g1);
        }
        __syncthreads();

        if (tid < 256) {
            int b = tid >> 2, u = tid & 3;
            float iv = gsmT[u * BB + b];
            float fv = gsmT[(4 + u) * BB + b];
            float gv = gsmT[(8 + u) * BB + b];
            float ov = gsmT[(12 + u) * BB + b];
            float c = sigf(fv) * csm[tid] + sigf(iv) * tanhf(gv);
            float h = sigf(ov) * tanhf(c);
            csm[tid] = c;
            __stcg(&hnxt[(cb + u) * BB + b], h);
            hseq[((size_t)t * BB + b) * HH + cb + u] = h;
        }
        grid_barrier(grp);
    }
}

// ------------------------------ LayerNorm ------------------------------------
__global__ __launch_bounds__(128)
void ln_kernel(const float* __restrict__ x, const float* __restrict__ gamma,
               const float* __restrict__ beta, float* __restrict__ y) {
    const int m = blockIdx.x;
    const int tid = threadIdx.x;
    __shared__ float red[4];
    float4 v = *(const float4*)(x + (size_t)m * HH + tid * 4);

    float s = v.x + v.y + v.z + v.w;
#pragma unroll
    for (int o = 16; o; o >>= 1) s += __shfl_down_sync(0xffffffffu, s, o);
    if ((tid & 31) == 0) red[tid >> 5] = s;
    __syncthreads();
    float mu = (red[0] + red[1] + red[2] + red[3]) * (1.f / HH);
    __syncthreads();

    float dx = v.x - mu, dy = v.y - mu, dz = v.z - mu, dw = v.w - mu;
    float s2 = dx * dx + dy * dy + dz * dz + dw * dw;
#pragma unroll
    for (int o = 16; o; o >>= 1) s2 += __shfl_down_sync(0xffffffffu, s2, o);
    if ((tid & 31) == 0) red[tid >> 5] = s2;
    __syncthreads();
    float var = (red[0] + red[1] + red[2] + red[3]) * (1.f / HH);
    float rs = rsqrtf(var + 1e-3f);

    float4 g = *(const float4*)(gamma + tid * 4);
    float4 b = *(const float4*)(beta + tid * 4);
    float4 o4;
    o4.x = dx * rs * g.x + b.x;
    o4.y = dy * rs * g.y + b.y;
    o4.z = dz * rs * g.z + b.z;
    o4.w = dw * rs * g.w + b.w;
    *(float4*)(y + (size_t)m * HH + tid * 4) = o4;
}

// ------------------------------ launch ---------------------------------------
extern "C" void kernel_launch(void* const* d_in, const int* in_sizes, int n_in,
                              void* d_out, int out_size) {
    const float* z     = (const float*)d_in[0];
    const float* Wp    = (const float*)d_in[1];
    const float* bp    = (const float*)d_in[2];
    const float* Ws    = (const float*)d_in[3];
    const float* bs    = (const float*)d_in[4];
    const float* K0    = (const float*)d_in[5];
    const float* R0    = (const float*)d_in[6];
    const float* b0    = (const float*)d_in[7];
    const float* K1    = (const float*)d_in[8];
    const float* R1    = (const float*)d_in[9];
    const float* b1    = (const float*)d_in[10];
    const float* K2    = (const float*)d_in[11];
    const float* R2    = (const float*)d_in[12];
    const float* b2    = (const float*)d_in[13];
    const float* gamma = (const float*)d_in[14];
    const float* beta  = (const float*)d_in[15];
    const float* W1    = (const float*)d_in[16];
    const float* b1d   = (const float*)d_in[17];
    const float* W2    = (const float*)d_in[18];
    const float* b2d   = (const float*)d_in[19];
    float* out = (float*)d_out;

    float *xk, *seqA, *seqB, *res, *W0eff, *b0eff;
    cudaGetSymbolAddress((void**)&xk,    d_xk);
    cudaGetSymbolAddress((void**)&seqA,  d_seqA);
    cudaGetSymbolAddress((void**)&seqB,  d_seqB);
    cudaGetSymbolAddress((void**)&res,   d_res);
    cudaGetSymbolAddress((void**)&W0eff, d_W0eff);
    cudaGetSymbolAddress((void**)&b0eff, d_b0eff);

    // idempotent, called every launch (no static guards allowed)
    const int lstm_smem = LSTM_SMEM_FLOATS * 4;  // ~134 KB
    cudaFuncSetAttribute(lstm_kernel,
                         cudaFuncAttributeMaxDynamicSharedMemorySize,
                         lstm_smem);

    // 1) fold: b0eff = bp@K0 + b0 ; W0eff = Wp@K0
    bias_fold_kernel<<<G4H / 32, 256>>>(bp, K0, b0);
    sgemm64<0,0,0><<<dim3(G4H/64, ZZ/64), 256>>>(Wp, K0, nullptr,
                                                 W0eff, ZZ, G4H, 2*HH);
    // 2) xK0 = z @ W0eff + b0eff   ([t][b] row order)
    sgemm128<1,0,0,1><<<dim3(G4H/128, MROWS/128), 256>>>(z, nullptr, W0eff, b0eff,
                                                         xk, MROWS, G4H, ZZ);
    // 3) LSTM 0 -> seqA
    lstm_kernel<<<LSTM_BLOCKS, 512, lstm_smem>>>(xk, R0, seqA);
    // 4) residual = z @ Ws + bs   ([t][b] row order)
    sgemm128<1,0,0,1><<<dim3(HH/128, MROWS/128), 256>>>(z, nullptr, Ws, bs,
                                                        res, MROWS, HH, ZZ);
    // 5) xK1 = seqA @ K1 + b1
    sgemm128<0,0,0,1><<<dim3(G4H/128, MROWS/128), 256>>>(seqA, nullptr, K1, b1,
                                                         xk, MROWS, G4H, HH);
    // 6) LSTM 1 -> seqB
    lstm_kernel<<<LSTM_BLOCKS, 512, lstm_smem>>>(xk, R1, seqB);
    // 7) xK2 = (seqB + res) @ K2 + b2
    sgemm128<0,0,1,1><<<dim3(G4H/128, MROWS/128), 256>>>(seqB, res, K2, b2,
                                                         xk, MROWS, G4H, HH);
    // 8) LSTM 2 -> seqA
    lstm_kernel<<<LSTM_BLOCKS, 512, lstm_smem>>>(xk, R2, seqA);
    // 9) LayerNorm: seqA -> seqB
    ln_kernel<<<MROWS, 128>>>(seqA, gamma, beta, seqB);
    // 10) y1 = relu(seqB @ W1 + b1d) -> seqA
    sgemm128<0,1,0,1><<<dim3(HH/128, MROWS/128), 256>>>(seqB, nullptr, W1, b1d,
                                                        seqA, MROWS, HH, HH);
    // 11) out = tanh(seqA @ W2 + b2d) -> d_out  ([b][t] row order)
    sgemm64<2,1,1><<<dim3(FF/64, MROWS/64), 256>>>(seqA, W2, b2d,
                                                   out, MROWS, FF, HH);
}

// round 11
// speedup vs baseline: 1.4683x; 1.4683x over previous
#include <cuda_runtime.h>
#include <math.h>

// Problem dims
#define BB 64
#define TT 256
#define ZZ 128
#define HH 512
#define FF 64
#define MROWS (BB*TT)      // 16384
#define G4H   (4*HH)       // 2048
#define LSTM_BLOCKS (HH/4) // 128

// ------------------------------ scratch buffers ------------------------------
__device__ float d_xk[MROWS * G4H];     // 134 MB  gate pre-activations
__device__ float d_seqA[MROWS * HH];
__device__ float d_seqB[MROWS * HH];
__device__ float d_res[MROWS * HH];
__device__ float d_W0eff[ZZ * G4H];
__device__ float d_b0eff[G4H];
__device__ float d_hT[2 * HH * BB];     // double-buffered h, [buf][hidden][batch]
__device__ unsigned g_grp[8];           // hierarchical barrier: 8 groups of 16
__device__ unsigned g_root;
__device__ unsigned g_gen;

__device__ __forceinline__ float sigf(float x) { return 1.f / (1.f + expf(-x)); }

// packed f32x2 helpers (used in LSTM only — proven win there; loses in GEMM)
#define FMA2(c, a, b) \
    asm("fma.rn.f32x2 %0, %2, %3, %1;" : "=l"(c) : "l"(c), "l"(a), "l"(b))
#define ADD2PK(d, a, b) \
    asm("add.rn.f32x2 %0, %1, %2;" : "=l"(d) : "l"(a), "l"(b))

__device__ __forceinline__ float f2lo(unsigned long long v) {
    return __uint_as_float((unsigned)v);
}
__device__ __forceinline__ float f2hi(unsigned long long v) {
    return __uint_as_float((unsigned)(v >> 32));
}

// ------------------------------ hierarchical grid barrier --------------------
__device__ __forceinline__ void grid_barrier(int grp) {
    __syncthreads();
    if (threadIdx.x == 0) {
        __threadfence();
        unsigned my = *(volatile unsigned*)&g_gen;
        if ((atomicAdd(&g_grp[grp], 1u) & 15u) == 15u) {
            if ((atomicAdd(&g_root, 1u) & 7u) == 7u) {
                atomicAdd(&g_gen, 1u);
            }
        }
        while (*(volatile unsigned*)&g_gen == my) {}
        __threadfence();
    }
    __syncthreads();
}

// ------------------------------ bias fold: b0eff = bp@K0 + b0 ----------------
__global__ void bias_fold_kernel(const float* __restrict__ bp,
                                 const float* __restrict__ K0,
                                 const float* __restrict__ b0) {
    __shared__ float red[8][32];
    const int c = threadIdx.x & 31, s = threadIdx.x >> 5;
    const int j = blockIdx.x * 32 + c;
    float acc = 0.f;
    for (int k = s * 128; k < s * 128 + 128; ++k)
        acc += bp[k] * K0[(size_t)k * G4H + j];
    red[s][c] = acc;
    __syncthreads();
    if (s == 0) {
        float t = 0.f;
#pragma unroll
        for (int r = 0; r < 8; ++r) t += red[r][c];
        d_b0eff[j] = t + b0[j];
    }
}

// ------------------------------ SGEMM 128x128x16, 8x8/thread, scalar FFMA ----
// Double-buffered K pipeline: one __syncthreads per chunk, LDG of chunk i+1
// overlapped with compute of chunk i.
// AMAP: 0 identity row, 1 (m=(t,b) -> source row b*T+t)
// ACT : 0 none, 1 relu
// ADD2A: A := A + A2 (identity-mapped rows)
// HASB: add bias[n]
template<int AMAP, int ACT, int ADD2A, int HASB>
__global__ __launch_bounds__(256, 2)
void sgemm128(const float* __restrict__ A, const float* __restrict__ A2,
              const float* __restrict__ Bm, const float* __restrict__ bias,
              float* __restrict__ C, int M, int N, int K) {
    __shared__ float As[2][16][128];
    __shared__ float Bs[2][16][128];
    const int tid = threadIdx.x;
    const int n0 = blockIdx.x * 128, m0 = blockIdx.y * 128;
    const int r = tid >> 2, kq = (tid & 3) * 4;
    const int kb = tid >> 5, n4 = (tid & 31) * 4;
    const int tm = tid >> 4, tn = tid & 15;

    float acc[8][8];
#pragma unroll
    for (int i = 0; i < 8; ++i)
#pragma unroll
        for (int j = 0; j < 8; ++j) acc[i][j] = 0.f;

    float4 sA0, sA1, sB0, sB1;

    // ---- stage chunk 0 into registers ----
    {
        const int k0 = 0;
#pragma unroll
        for (int h = 0; h < 2; ++h) {
            int rr = r + h * 64;
            int m = m0 + rr;
            int arow = (AMAP == 1) ? ((m & 63) * TT + (m >> 6)) : m;
            float4 av = *(const float4*)(A + (size_t)arow * K + k0 + kq);
            if (ADD2A) {
                float4 a2 = *(const float4*)(A2 + (size_t)m * K + k0 + kq);
                av.x += a2.x; av.y += a2.y; av.z += a2.z; av.w += a2.w;
            }
            float4 bv = *(const float4*)(Bm + (size_t)(k0 + kb + h * 8) * N + n0 + n4);
            if (h == 0) { sA0 = av; sB0 = bv; } else { sA1 = av; sB1 = bv; }
        }
    }

    int cur = 0;
    for (int k0 = 0; k0 < K; k0 += 16, cur ^= 1) {
        // store staged regs into buf[cur] (A transposed)
        As[cur][kq + 0][r]      = sA0.x;
        As[cur][kq + 1][r]      = sA0.y;
        As[cur][kq + 2][r]      = sA0.z;
        As[cur][kq + 3][r]      = sA0.w;
        As[cur][kq + 0][r + 64] = sA1.x;
        As[cur][kq + 1][r + 64] = sA1.y;
        As[cur][kq + 2][r + 64] = sA1.z;
        As[cur][kq + 3][r + 64] = sA1.w;
        *(float4*)&Bs[cur][kb][n4]     = sB0;
        *(float4*)&Bs[cur][kb + 8][n4] = sB1;

        // prefetch chunk k0+16 (overlaps with compute below)
        if (k0 + 16 < K) {
            const int kn = k0 + 16;
#pragma unroll
            for (int h = 0; h < 2; ++h) {
                int rr = r + h * 64;
                int m = m0 + rr;
                int arow = (AMAP == 1) ? ((m & 63) * TT + (m >> 6)) : m;
                float4 av = *(const float4*)(A + (size_t)arow * K + kn + kq);
                if (ADD2A) {
                    float4 a2 = *(const float4*)(A2 + (size_t)m * K + kn + kq);
                    av.x += a2.x; av.y += a2.y; av.z += a2.z; av.w += a2.w;
                }
                float4 bv = *(const float4*)(Bm + (size_t)(kn + kb + h * 8) * N + n0 + n4);
                if (h == 0) { sA0 = av; sB0 = bv; } else { sA1 = av; sB1 = bv; }
            }
        }
        __syncthreads();
#pragma unroll
        for (int k = 0; k < 16; ++k) {
            float4 a0 = *(const float4*)&As[cur][k][tm * 8];
            float4 a1 = *(const float4*)&As[cur][k][tm * 8 + 4];
            float4 b0 = *(const float4*)&Bs[cur][k][tn * 8];
            float4 b1 = *(const float4*)&Bs[cur][k][tn * 8 + 4];
            float ar[8] = {a0.x, a0.y, a0.z, a0.w, a1.x, a1.y, a1.z, a1.w};
            float br[8] = {b0.x, b0.y, b0.z, b0.w, b1.x, b1.y, b1.z, b1.w};
#pragma unroll
            for (int i = 0; i < 8; ++i)
#pragma unroll
                for (int j = 0; j < 8; ++j) acc[i][j] += ar[i] * br[j];
        }
    }

#pragma unroll
    for (int i = 0; i < 8; ++i) {
        int m = m0 + tm * 8 + i;
        size_t ro = (size_t)m * N;
        float vals[8];
#pragma unroll
        for (int j = 0; j < 8; ++j) {
            int n = n0 + tn * 8 + j;
            float t = acc[i][j];
            if (HASB) t += bias[n];
            if (ACT == 1) t = fmaxf(t, 0.f);
            vals[j] = t;
        }
        *(float4*)(C + ro + n0 + tn * 8)     = make_float4(vals[0], vals[1], vals[2], vals[3]);
        *(float4*)(C + ro + n0 + tn * 8 + 4) = make_float4(vals[4], vals[5], vals[6], vals[7]);
    }
}

// ------------------------------ SGEMM 64x64x16 (small shapes) ----------------
// OMAP: 0 identity, 1 (t,b)->(b,t) output rows ; ACT: 0 none, 2 tanh
template<int ACT, int OMAP, int HASB>
__global__ __launch_bounds__(256)
void sgemm64(const float* __restrict__ A, const float* __restrict__ Bm,
             const float* __restrict__ bias, float* __restrict__ C,
             int M, int N, int K) {
    __shared__ float As[16][64];
    __shared__ float Bs[16][64];
    const int tid = threadIdx.x;
    const int tx = tid & 15, ty = tid >> 4;
    const int n0 = blockIdx.x * 64, m0 = blockIdx.y * 64;

    float acc[4][4];
#pragma unroll
    for (int i = 0; i < 4; ++i)
#pragma unroll
        for (int j = 0; j < 4; ++j) acc[i][j] = 0.f;

    const int arowl = tid >> 2;
    const int kq = (tid & 3) * 4;
    const int krow = tid >> 4;
    const int nq = (tid & 15) * 4;

    for (int k0 = 0; k0 < K; k0 += 16) {
        {
            int m = m0 + arowl;
            float4 av = *(const float4*)(A + (size_t)m * K + k0 + kq);
            As[kq + 0][arowl] = av.x;
            As[kq + 1][arowl] = av.y;
            As[kq + 2][arowl] = av.z;
            As[kq + 3][arowl] = av.w;
        }
        *(float4*)&Bs[krow][nq] =
            *(const float4*)(Bm + (size_t)(k0 + krow) * N + n0 + nq);
        __syncthreads();
#pragma unroll
        for (int k = 0; k < 16; ++k) {
            float4 a = *(const float4*)&As[k][ty * 4];
            float4 b = *(const float4*)&Bs[k][tx * 4];
            float ar[4] = {a.x, a.y, a.z, a.w};
            float br[4] = {b.x, b.y, b.z, b.w};
#pragma unroll
            for (int i = 0; i < 4; ++i)
#pragma unroll
                for (int j = 0; j < 4; ++j) acc[i][j] += ar[i] * br[j];
        }
        __syncthreads();
    }

#pragma unroll
    for (int i = 0; i < 4; ++i) {
        int m = m0 + ty * 4 + i;
        size_t ro = (OMAP == 1) ? (size_t)((m & 63) * TT + (m >> 6)) * N
                                : (size_t)m * N;
        float4 v;
        float* vp = (float*)&v;
#pragma unroll
        for (int j = 0; j < 4; ++j) {
            int n = n0 + tx * 4 + j;
            float t = acc[i][j];
            if (HASB) t += bias[n];
            if (ACT == 2) t = tanhf(t);
            vp[j] = t;
        }
        *(float4*)(C + ro + n0 + tx * 4) = v;
    }
}

// ------------------------------ LSTM recurrence v4 (unchanged) ---------------
#define LSTM_SMEM_FLOATS (16384 + 16384 + 1024 + 256)
__global__ __launch_bounds__(512)
void lstm_kernel(const float* __restrict__ xk, const float* __restrict__ R,
                 float* __restrict__ hseq) {
    extern __shared__ float smem[];
    float* pw   = smem;                  // 16384 floats: per-warp partials
    float* Rdup = smem + 16384;          // 16384 floats: duplicated R slice
    float* gsmT = smem + 32768;          // 1024 floats [j][b]
    float* csm  = gsmT + 1024;           // 256 floats

    const int tid = threadIdx.x;
    const int cb  = blockIdx.x * 4;
    const int grp = blockIdx.x >> 4;

    for (int idx = tid; idx < HH * 16; idx += 512) {
        int k = idx >> 4, j = idx & 15;
        float v = R[(size_t)k * G4H + (j >> 2) * HH + cb + (j & 3)];
        Rdup[k * 32 + j * 2]     = v;
        Rdup[k * 32 + j * 2 + 1] = v;
    }
    if (tid < 256)
        __stcg(&d_hT[(cb + (tid >> 6)) * BB + (tid & 63)], 0.f);
    if (tid < 256) csm[tid] = 0.f;
    grid_barrier(grp);

    const int lane = tid & 31;
    const int wi   = tid >> 5;       // warp: k-range [32wi, 32wi+32)
    const int jg   = lane >> 4;      // col group (8 cols each)
    const int bg   = lane & 15;      // batch quad

    const ulonglong2* RdU2 = (const ulonglong2*)Rdup;

    const int rj   = tid >> 5;       // gate col 0..15
    const int rbp  = tid & 31;       // batch pair 0..31
    const int rb0  = rbp * 2;
    const int rcol = (rj >> 2) * HH + cb + (rj & 3);

    for (int t = 0; t < TT; ++t) {
        const float* hcur = d_hT + (t & 1) * (HH * BB);
        float* hnxt       = d_hT + ((t + 1) & 1) * (HH * BB);
        const float* xkt  = xk + (size_t)t * BB * G4H;

        float xpre0 = __ldg(xkt + (size_t)rb0 * G4H + rcol);
        float xpre1 = __ldg(xkt + (size_t)(rb0 + 1) * G4H + rcol);

        unsigned long long acc2[8][2];
#pragma unroll
        for (int i = 0; i < 8; ++i) { acc2[i][0] = 0ULL; acc2[i][1] = 0ULL; }

        const double2* hp = (const double2*)(hcur + wi * 32 * 64 + bg * 4);
        const ulonglong2* rp = RdU2 + wi * 32 * 8 + jg * 4;
#pragma unroll 8
        for (int kk = 0; kk < 32; ++kk) {
            double2 hd = __ldcg(hp + kk * 16);
            unsigned long long h01 = __double_as_longlong(hd.x);
            unsigned long long h23 = __double_as_longlong(hd.y);
            const ulonglong2* rr = rp + kk * 8;
#pragma unroll
            for (int i = 0; i < 4; ++i) {
                ulonglong2 rv = rr[i];
                FMA2(acc2[2 * i][0],     rv.x, h01);
                FMA2(acc2[2 * i][1],     rv.x, h23);
                FMA2(acc2[2 * i + 1][0], rv.y, h01);
                FMA2(acc2[2 * i + 1][1], rv.y, h23);
            }
        }

        {
            float4* pw4 = (float4*)pw;
#pragma unroll
            for (int ji = 0; ji < 8; ++ji) {
                int j = jg * 8 + ji;
                float4 v;
                v.x = f2lo(acc2[ji][0]); v.y = f2hi(acc2[ji][0]);
                v.z = f2lo(acc2[ji][1]); v.w = f2hi(acc2[ji][1]);
                pw4[wi * 256 + j * 16 + bg] = v;
            }
        }
        __syncthreads();

        {
            const unsigned long long* pw2 = (const unsigned long long*)pw;
            unsigned long long a = pw2[rj * 32 + rbp];
#pragma unroll
            for (int w2 = 1; w2 < 16; ++w2) {
                unsigned long long o = pw2[w2 * 512 + rj * 32 + rbp];
                ADD2PK(a, a, o);
            }
            float g0 = f2lo(a) + xpre0;
            float g1 = f2hi(a) + xpre1;
            ((float2*)gsmT)[rj * 32 + rbp] = make_float2(g0, g1);
        }
        __syncthreads();

        if (tid < 256) {
            int b = tid >> 2, u = tid & 3;
            float iv = gsmT[u * BB + b];
            float fv = gsmT[(4 + u) * BB + b];
            float gv = gsmT[(8 + u) * BB + b];
            float ov = gsmT[(12 + u) * BB + b];
            float c = sigf(fv) * csm[tid] + sigf(iv) * tanhf(gv);
            float h = sigf(ov) * tanhf(c);
            csm[tid] = c;
            __stcg(&hnxt[(cb + u) * BB + b], h);
            hseq[((size_t)t * BB + b) * HH + cb + u] = h;
        }
        grid_barrier(grp);
    }
}

// ------------------------------ LayerNorm ------------------------------------
__global__ __launch_bounds__(128)
void ln_kernel(const float* __restrict__ x, const float* __restrict__ gamma,
               const float* __restrict__ beta, float* __restrict__ y) {
    const int m = blockIdx.x;
    const int tid = threadIdx.x;
    __shared__ float red[4];
    float4 v = *(const float4*)(x + (size_t)m * HH + tid * 4);

    float s = v.x + v.y + v.z + v.w;
#pragma unroll
    for (int o = 16; o; o >>= 1) s += __shfl_down_sync(0xffffffffu, s, o);
    if ((tid & 31) == 0) red[tid >> 5] = s;
    __syncthreads();
    float mu = (red[0] + red[1] + red[2] + red[3]) * (1.f / HH);
    __syncthreads();

    float dx = v.x - mu, dy = v.y - mu, dz = v.z - mu, dw = v.w - mu;
    float s2 = dx * dx + dy * dy + dz * dz + dw * dw;
#pragma unroll
    for (int o = 16; o; o >>= 1) s2 += __shfl_down_sync(0xffffffffu, s2, o);
    if ((tid & 31) == 0) red[tid >> 5] = s2;
    __syncthreads();
    float var = (red[0] + red[1] + red[2] + red[3]) * (1.f / HH);
    float rs = rsqrtf(var + 1e-3f);

    float4 g = *(const float4*)(gamma + tid * 4);
    float4 b = *(const float4*)(beta + tid * 4);
    float4 o4;
    o4.x = dx * rs * g.x + b.x;
    o4.y = dy * rs * g.y + b.y;
    o4.z = dz * rs * g.z + b.z;
    o4.w = dw * rs * g.w + b.w;
    *(float4*)(y + (size_t)m * HH + tid * 4) = o4;
}

// ------------------------------ launch ---------------------------------------
extern "C" void kernel_launch(void* const* d_in, const int* in_sizes, int n_in,
                              void* d_out, int out_size) {
    const float* z     = (const float*)d_in[0];
    const float* Wp    = (const float*)d_in[1];
    const float* bp    = (const float*)d_in[2];
    const float* Ws    = (const float*)d_in[3];
    const float* bs    = (const float*)d_in[4];
    const float* K0    = (const float*)d_in[5];
    const float* R0    = (const float*)d_in[6];
    const float* b0    = (const float*)d_in[7];
    const float* K1    = (const float*)d_in[8];
    const float* R1    = (const float*)d_in[9];
    const float* b1    = (const float*)d_in[10];
    const float* K2    = (const float*)d_in[11];
    const float* R2    = (const float*)d_in[12];
    const float* b2    = (const float*)d_in[13];
    const float* gamma = (const float*)d_in[14];
    const float* beta  = (const float*)d_in[15];
    const float* W1    = (const float*)d_in[16];
    const float* b1d   = (const float*)d_in[17];
    const float* W2    = (const float*)d_in[18];
    const float* b2d   = (const float*)d_in[19];
    float* out = (float*)d_out;

    float *xk, *seqA, *seqB, *res, *W0eff, *b0eff;
    cudaGetSymbolAddress((void**)&xk,    d_xk);
    cudaGetSymbolAddress((void**)&seqA,  d_seqA);
    cudaGetSymbolAddress((void**)&seqB,  d_seqB);
    cudaGetSymbolAddress((void**)&res,   d_res);
    cudaGetSymbolAddress((void**)&W0eff, d_W0eff);
    cudaGetSymbolAddress((void**)&b0eff, d_b0eff);

    // idempotent, called every launch (no static guards allowed)
    const int lstm_smem = LSTM_SMEM_FLOATS * 4;  // ~134 KB
    cudaFuncSetAttribute(lstm_kernel,
                         cudaFuncAttributeMaxDynamicSharedMemorySize,
                         lstm_smem);

    // 1) fold: b0eff = bp@K0 + b0 ; W0eff = Wp@K0
    bias_fold_kernel<<<G4H / 32, 256>>>(bp, K0, b0);
    sgemm64<0,0,0><<<dim3(G4H/64, ZZ/64), 256>>>(Wp, K0, nullptr,
                                                 W0eff, ZZ, G4H, 2*HH);
    // 2) xK0 = z @ W0eff + b0eff   ([t][b] row order)
    sgemm128<1,0,0,1><<<dim3(G4H/128, MROWS/128), 256>>>(z, nullptr, W0eff, b0eff,
                                                         xk, MROWS, G4H, ZZ);
    // 3) LSTM 0 -> seqA
    lstm_kernel<<<LSTM_BLOCKS, 512, lstm_smem>>>(xk, R0, seqA);
    // 4) residual = z @ Ws + bs   ([t][b] row order)
    sgemm128<1,0,0,1><<<dim3(HH/128, MROWS/128), 256>>>(z, nullptr, Ws, bs,
                                                        res, MROWS, HH, ZZ);
    // 5) xK1 = seqA @ K1 + b1
    sgemm128<0,0,0,1><<<dim3(G4H/128, MROWS/128), 256>>>(seqA, nullptr, K1, b1,
                                                         xk, MROWS, G4H, HH);
    // 6) LSTM 1 -> seqB
    lstm_kernel<<<LSTM_BLOCKS, 512, lstm_smem>>>(xk, R1, seqB);
    // 7) xK2 = (seqB + res) @ K2 + b2
    sgemm128<0,0,1,1><<<dim3(G4H/128, MROWS/128), 256>>>(seqB, res, K2, b2,
                                                         xk, MROWS, G4H, HH);
    // 8) LSTM 2 -> seqA
    lstm_kernel<<<LSTM_BLOCKS, 512, lstm_smem>>>(xk, R2, seqA);
    // 9) LayerNorm: seqA -> seqB
    ln_kernel<<<MROWS, 128>>>(seqA, gamma, beta, seqB);
    // 10) y1 = relu(seqB @ W1 + b1d) -> seqA
    sgemm128<0,1,0,1><<<dim3(HH/128, MROWS/128), 256>>>(seqB, nullptr, W1, b1d,
                                                        seqA, MROWS, HH, HH);
    // 11) out = tanh(seqA @ W2 + b2d) -> d_out  ([b][t] row order)
    sgemm64<2,1,1><<<dim3(FF/64, MROWS/64), 256>>>(seqA, W2, b2d,
                                                   out, MROWS, FF, HH);
}

// round 13
// speedup vs baseline: 1.6018x; 1.0909x over previous
#include <cuda_runtime.h>
#include <cuda_bf16.h>
#include <math.h>

// Problem dims
#define BB 64
#define TT 256
#define ZZ 128
#define HH 512
#define FF 64
#define MROWS (BB*TT)      // 16384
#define G4H   (4*HH)       // 2048
#define LSTM_BLOCKS (HH/4) // 128

// ------------------------------ scratch buffers ------------------------------
__device__ float d_xk[MROWS * G4H];     // 134 MB  gate pre-activations
__device__ float d_seqA[MROWS * HH];
__device__ float d_seqB[MROWS * HH];
__device__ float d_res[MROWS * HH];
__device__ float d_W0eff[ZZ * G4H];
__device__ float d_b0eff[G4H];
__device__ float d_hT[2 * HH * BB];     // double-buffered h
__device__ __nv_bfloat16 d_Xh[MROWS * HH];   // bf16 hi of activations
__device__ __nv_bfloat16 d_Xl[MROWS * HH];   // bf16 lo
__device__ __nv_bfloat16 d_Wh[G4H * HH];     // bf16 hi of W^T [n][k]
__device__ __nv_bfloat16 d_Wl[G4H * HH];     // bf16 lo
__device__ unsigned g_grp[8];
__device__ unsigned g_root;
__device__ unsigned g_gen;

// fast gate nonlinearities (MUFU EX2 path, rel err ~1e-6)
__device__ __forceinline__ float fsig(float x)  { return __fdividef(1.f, 1.f + __expf(-x)); }
__device__ __forceinline__ float ftanh(float x) { return 1.f - __fdividef(2.f, 1.f + __expf(2.f * x)); }

// packed f32x2 helpers (LSTM only)
#define FMA2(c, a, b) \
    asm("fma.rn.f32x2 %0, %2, %3, %1;" : "=l"(c) : "l"(c), "l"(a), "l"(b))
#define ADD2PK(d, a, b) \
    asm("add.rn.f32x2 %0, %1, %2;" : "=l"(d) : "l"(a), "l"(b))

__device__ __forceinline__ float f2lo(unsigned long long v) { return __uint_as_float((unsigned)v); }
__device__ __forceinline__ float f2hi(unsigned long long v) { return __uint_as_float((unsigned)(v >> 32)); }

__device__ __forceinline__ unsigned smem_u32(const void* p) {
    unsigned a;
    asm("{ .reg .u64 t; cvta.to.shared.u64 t, %1; cvt.u32.u64 %0, t; }" : "=r"(a) : "l"(p));
    return a;
}

// ------------------------------ mma.sync helpers (non-'a' ISA, sm_80+) -------
__device__ __forceinline__ void ldsm4(unsigned* r, unsigned addr) {
    asm volatile("ldmatrix.sync.aligned.m8n8.x4.shared.b16 {%0,%1,%2,%3}, [%4];"
                 : "=r"(r[0]), "=r"(r[1]), "=r"(r[2]), "=r"(r[3]) : "r"(addr));
}
__device__ __forceinline__ void mma16816(float* c, const unsigned* a, const unsigned* b) {
    asm volatile(
        "mma.sync.aligned.m16n8k16.row.col.f32.bf16.bf16.f32 "
        "{%0,%1,%2,%3}, {%4,%5,%6,%7}, {%8,%9}, {%0,%1,%2,%3};"
        : "+f"(c[0]), "+f"(c[1]), "+f"(c[2]), "+f"(c[3])
        : "r"(a[0]), "r"(a[1]), "r"(a[2]), "r"(a[3]), "r"(b[0]), "r"(b[1]));
}

// ------------------------------ bf16 conversion kernels ----------------------
// W [512][2048] fp32 -> Wh/Wl [2048][512] bf16 (transposed to K-major)
__global__ void convW_kernel(const float* __restrict__ W) {
    int id = blockIdx.x * 256 + threadIdx.x;
    int k = id & (HH - 1), n = id >> 9;
    float v = W[(size_t)k * G4H + n];
    __nv_bfloat16 h = __float2bfloat16(v);
    d_Wh[id] = h;
    d_Wl[id] = __float2bfloat16(v - __bfloat162float(h));
}
// X (= A or A+A2) [16384][512] fp32 -> Xh/Xl bf16
template<int ADD2>
__global__ void convA_kernel(const float* __restrict__ A, const float* __restrict__ A2) {
    int id = blockIdx.x * 256 + threadIdx.x;
    float v = A[id];
    if (ADD2) v += A2[id];
    __nv_bfloat16 h = __float2bfloat16(v);
    d_Xh[id] = h;
    d_Xl[id] = __float2bfloat16(v - __bfloat162float(h));
}

// ------------------------------ bf16x3 mma.sync GEMM -------------------------
// D[16384,2048] = X[16384,512] @ W[512,2048] + bias, fp32 out.
// Block 128x64, 8 warps (warp tile 32x32), K chunks of 32, bf16x3 (AhBh+AhBl+AlBh).
#define PADK 40   // 32 k + 8 pad -> 80B row stride, conflict-free LDSM
__global__ __launch_bounds__(256)
void mma_gemm_kernel(const __nv_bfloat16* __restrict__ Xh,
                     const __nv_bfloat16* __restrict__ Xl,
                     const __nv_bfloat16* __restrict__ Wh,
                     const __nv_bfloat16* __restrict__ Wl,
                     const float* __restrict__ bias,
                     float* __restrict__ out) {
    __shared__ __nv_bfloat16 Ah[128 * PADK], Al[128 * PADK];
    __shared__ __nv_bfloat16 Bh[64 * PADK],  Bl[64 * PADK];
    const int tid = threadIdx.x, lane = tid & 31, wid = tid >> 5;
    const int n0 = blockIdx.x * 64, m0 = blockIdx.y * 128;
    const int wm = (wid & 3) * 32, wn = (wid >> 2) * 32;

    float acc[2][4][4];
#pragma unroll
    for (int mt = 0; mt < 2; ++mt)
#pragma unroll
        for (int nt = 0; nt < 4; ++nt)
#pragma unroll
            for (int i = 0; i < 4; ++i) acc[mt][nt][i] = 0.f;

    // per-lane ldmatrix row/koff
    const int aRow = lane & 15;
    const int aK   = (lane >> 4) * 8;
    const int bRow = ((lane >> 4) & 1) * 8 + (lane & 7);
    const int bK   = ((lane >> 3) & 1) * 8;
    const unsigned ahb = smem_u32(Ah), alb = smem_u32(Al);
    const unsigned bhb = smem_u32(Bh), blb = smem_u32(Bl);

    const int ldrow = tid >> 2, ldseg = (tid & 3) * 8;

    for (int kc = 0; kc < 16; ++kc) {
        const int kg = kc * 32;
        // A tiles: 128 rows x 32 k (hi+lo)
#pragma unroll
        for (int i = 0; i < 2; ++i) {
            int row = ldrow + i * 64;
            size_t g = (size_t)(m0 + row) * HH + kg + ldseg;
            *(uint4*)&Ah[row * PADK + ldseg] = *(const uint4*)(Xh + g);
            *(uint4*)&Al[row * PADK + ldseg] = *(const uint4*)(Xl + g);
        }
        // B tiles: 64 rows x 32 k (hi+lo)
        {
            size_t g = (size_t)(n0 + ldrow) * HH + kg + ldseg;
            *(uint4*)&Bh[ldrow * PADK + ldseg] = *(const uint4*)(Wh + g);
            *(uint4*)&Bl[ldrow * PADK + ldseg] = *(const uint4*)(Wl + g);
        }
        __syncthreads();
#pragma unroll
        for (int q = 0; q < 2; ++q) {
            unsigned fah[2][4], fal[2][4], fbh[2][4], fbl[2][4];
#pragma unroll
            for (int mt = 0; mt < 2; ++mt) {
                unsigned off = (unsigned)(((wm + mt * 16 + aRow) * PADK + q * 16 + aK) * 2);
                ldsm4(fah[mt], ahb + off);
                ldsm4(fal[mt], alb + off);
            }
#pragma unroll
            for (int np = 0; np < 2; ++np) {
                unsigned off = (unsigned)(((wn + np * 16 + bRow) * PADK + q * 16 + bK) * 2);
                ldsm4(fbh[np], bhb + off);
                ldsm4(fbl[np], blb + off);
            }
#pragma unroll
            for (int mt = 0; mt < 2; ++mt)
#pragma unroll
                for (int nt = 0; nt < 4; ++nt) {
                    const unsigned* bh2 = &fbh[nt >> 1][(nt & 1) * 2];
                    const unsigned* bl2 = &fbl[nt >> 1][(nt & 1) * 2];
                    mma16816(acc[mt][nt], fah[mt], bh2);
                    mma16816(acc[mt][nt], fah[mt], bl2);
                    mma16816(acc[mt][nt], fal[mt], bh2);
                }
        }
        __syncthreads();
    }

    // epilogue: c0,c1 = (r, cp..cp+1); c2,c3 = (r+8, ..)
    const int r = lane >> 2, cp = (lane & 3) * 2;
#pragma unroll
    for (int mt = 0; mt < 2; ++mt) {
        int m_lo = m0 + wm + mt * 16 + r;
        int m_hi = m_lo + 8;
#pragma unroll
        for (int nt = 0; nt < 4; ++nt) {
            int n = n0 + wn + nt * 8 + cp;
            float b0 = bias[n], b1 = bias[n + 1];
            float2 v0 = make_float2(acc[mt][nt][0] + b0, acc[mt][nt][1] + b1);
            float2 v1 = make_float2(acc[mt][nt][2] + b0, acc[mt][nt][3] + b1);
            *(float2*)(out + (size_t)m_lo * G4H + n) = v0;
            *(float2*)(out + (size_t)m_hi * G4H + n) = v1;
        }
    }
}

// ------------------------------ hierarchical grid barrier --------------------
__device__ __forceinline__ void grid_barrier(int grp) {
    __syncthreads();
    if (threadIdx.x == 0) {
        __threadfence();
        unsigned my = *(volatile unsigned*)&g_gen;
        if ((atomicAdd(&g_grp[grp], 1u) & 15u) == 15u) {
            if ((atomicAdd(&g_root, 1u) & 7u) == 7u) {
                atomicAdd(&g_gen, 1u);
            }
        }
        while (*(volatile unsigned*)&g_gen == my) {}
        __threadfence();
    }
    __syncthreads();
}

// ------------------------------ bias fold ------------------------------------
__global__ void bias_fold_kernel(const float* __restrict__ bp,
                                 const float* __restrict__ K0,
                                 const float* __restrict__ b0) {
    __shared__ float red[8][32];
    const int c = threadIdx.x & 31, s = threadIdx.x >> 5;
    const int j = blockIdx.x * 32 + c;
    float acc = 0.f;
    for (int k = s * 128; k < s * 128 + 128; ++k)
        acc += bp[k] * K0[(size_t)k * G4H + j];
    red[s][c] = acc;
    __syncthreads();
    if (s == 0) {
        float t = 0.f;
#pragma unroll
        for (int r = 0; r < 8; ++r) t += red[r][c];
        d_b0eff[j] = t + b0[j];
    }
}

// ------------------------------ SGEMM 128x128x16 (scalar FFMA) ---------------
template<int AMAP, int ACT, int ADD2A, int HASB>
__global__ __launch_bounds__(256, 2)
void sgemm128(const float* __restrict__ A, const float* __restrict__ A2,
              const float* __restrict__ Bm, const float* __restrict__ bias,
              float* __restrict__ C, int M, int N, int K) {
    __shared__ float As[2][16][128];
    __shared__ float Bs[2][16][128];
    const int tid = threadIdx.x;
    const int n0 = blockIdx.x * 128, m0 = blockIdx.y * 128;
    const int r = tid >> 2, kq = (tid & 3) * 4;
    const int kb = tid >> 5, n4 = (tid & 31) * 4;
    const int tm = tid >> 4, tn = tid & 15;

    float acc[8][8];
#pragma unroll
    for (int i = 0; i < 8; ++i)
#pragma unroll
        for (int j = 0; j < 8; ++j) acc[i][j] = 0.f;

    float4 sA0, sA1, sB0, sB1;
    {
        const int k0 = 0;
#pragma unroll
        for (int h = 0; h < 2; ++h) {
            int rr = r + h * 64;
            int m = m0 + rr;
            int arow = (AMAP == 1) ? ((m & 63) * TT + (m >> 6)) : m;
            float4 av = *(const float4*)(A + (size_t)arow * K + k0 + kq);
            if (ADD2A) {
                float4 a2 = *(const float4*)(A2 + (size_t)m * K + k0 + kq);
                av.x += a2.x; av.y += a2.y; av.z += a2.z; av.w += a2.w;
            }
            float4 bv = *(const float4*)(Bm + (size_t)(k0 + kb + h * 8) * N + n0 + n4);
            if (h == 0) { sA0 = av; sB0 = bv; } else { sA1 = av; sB1 = bv; }
        }
    }
    int cur = 0;
    for (int k0 = 0; k0 < K; k0 += 16, cur ^= 1) {
        As[cur][kq + 0][r]      = sA0.x;
        As[cur][kq + 1][r]      = sA0.y;
        As[cur][kq + 2][r]      = sA0.z;
        As[cur][kq + 3][r]      = sA0.w;
        As[cur][kq + 0][r + 64] = sA1.x;
        As[cur][kq + 1][r + 64] = sA1.y;
        As[cur][kq + 2][r + 64] = sA1.z;
        As[cur][kq + 3][r + 64] = sA1.w;
        *(float4*)&Bs[cur][kb][n4]     = sB0;
        *(float4*)&Bs[cur][kb + 8][n4] = sB1;

        if (k0 + 16 < K) {
            const int kn = k0 + 16;
#pragma unroll
            for (int h = 0; h < 2; ++h) {
                int rr = r + h * 64;
                int m = m0 + rr;
                int arow = (AMAP == 1) ? ((m & 63) * TT + (m >> 6)) : m;
                float4 av = *(const float4*)(A + (size_t)arow * K + kn + kq);
                if (ADD2A) {
                    float4 a2 = *(const float4*)(A2 + (size_t)m * K + kn + kq);
                    av.x += a2.x; av.y += a2.y; av.z += a2.z; av.w += a2.w;
                }
                float4 bv = *(const float4*)(Bm + (size_t)(kn + kb + h * 8) * N + n0 + n4);
                if (h == 0) { sA0 = av; sB0 = bv; } else { sA1 = av; sB1 = bv; }
            }
        }
        __syncthreads();
#pragma unroll
        for (int k = 0; k < 16; ++k) {
            float4 a0 = *(const float4*)&As[cur][k][tm * 8];
            float4 a1 = *(const float4*)&As[cur][k][tm * 8 + 4];
            float4 b0 = *(const float4*)&Bs[cur][k][tn * 8];
            float4 b1 = *(const float4*)&Bs[cur][k][tn * 8 + 4];
            float ar[8] = {a0.x, a0.y, a0.z, a0.w, a1.x, a1.y, a1.z, a1.w};
            float br[8] = {b0.x, b0.y, b0.z, b0.w, b1.x, b1.y, b1.z, b1.w};
#pragma unroll
            for (int i = 0; i < 8; ++i)
#pragma unroll
                for (int j = 0; j < 8; ++j) acc[i][j] += ar[i] * br[j];
        }
    }

#pragma unroll
    for (int i = 0; i < 8; ++i) {
        int m = m0 + tm * 8 + i;
        size_t ro = (size_t)m * N;
        float vals[8];
#pragma unroll
        for (int j = 0; j < 8; ++j) {
            int n = n0 + tn * 8 + j;
            float t = acc[i][j];
            if (HASB) t += bias[n];
            if (ACT == 1) t = fmaxf(t, 0.f);
            vals[j] = t;
        }
        *(float4*)(C + ro + n0 + tn * 8)     = make_float4(vals[0], vals[1], vals[2], vals[3]);
        *(float4*)(C + ro + n0 + tn * 8 + 4) = make_float4(vals[4], vals[5], vals[6], vals[7]);
    }
}

// ------------------------------ SGEMM 64x64x16 (small shapes) ----------------
template<int ACT, int OMAP, int HASB>
__global__ __launch_bounds__(256)
void sgemm64(const float* __restrict__ A, const float* __restrict__ Bm,
             const float* __restrict__ bias, float* __restrict__ C,
             int M, int N, int K) {
    __shared__ float As[16][64];
    __shared__ float Bs[16][64];
    const int tid = threadIdx.x;
    const int tx = tid & 15, ty = tid >> 4;
    const int n0 = blockIdx.x * 64, m0 = blockIdx.y * 64;

    float acc[4][4];
#pragma unroll
    for (int i = 0; i < 4; ++i)
#pragma unroll
        for (int j = 0; j < 4; ++j) acc[i][j] = 0.f;

    const int arowl = tid >> 2;
    const int kq = (tid & 3) * 4;
    const int krow = tid >> 4;
    const int nq = (tid & 15) * 4;

    for (int k0 = 0; k0 < K; k0 += 16) {
        {
            int m = m0 + arowl;
            float4 av = *(const float4*)(A + (size_t)m * K + k0 + kq);
            As[kq + 0][arowl] = av.x;
            As[kq + 1][arowl] = av.y;
            As[kq + 2][arowl] = av.z;
            As[kq + 3][arowl] = av.w;
        }
        *(float4*)&Bs[krow][nq] =
            *(const float4*)(Bm + (size_t)(k0 + krow) * N + n0 + nq);
        __syncthreads();
#pragma unroll
        for (int k = 0; k < 16; ++k) {
            float4 a = *(const float4*)&As[k][ty * 4];
            float4 b = *(const float4*)&Bs[k][tx * 4];
            float ar[4] = {a.x, a.y, a.z, a.w};
            float br[4] = {b.x, b.y, b.z, b.w};
#pragma unroll
            for (int i = 0; i < 4; ++i)
#pragma unroll
                for (int j = 0; j < 4; ++j) acc[i][j] += ar[i] * br[j];
        }
        __syncthreads();
    }

#pragma unroll
    for (int i = 0; i < 4; ++i) {
        int m = m0 + ty * 4 + i;
        size_t ro = (OMAP == 1) ? (size_t)((m & 63) * TT + (m >> 6)) * N
                                : (size_t)m * N;
        float4 v;
        float* vp = (float*)&v;
#pragma unroll
        for (int j = 0; j < 4; ++j) {
            int n = n0 + tx * 4 + j;
            float t = acc[i][j];
            if (HASB) t += bias[n];
            if (ACT == 2) t = tanhf(t);
            vp[j] = t;
        }
        *(float4*)(C + ro + n0 + tx * 4) = v;
    }
}

// ------------------------------ LSTM recurrence v4 ---------------------------
#define LSTM_SMEM_FLOATS (16384 + 16384 + 1024 + 256)
__global__ __launch_bounds__(512)
void lstm_kernel(const float* __restrict__ xk, const float* __restrict__ R,
                 float* __restrict__ hseq) {
    extern __shared__ float smemf[];
    float* pw   = smemf;
    float* Rdup = smemf + 16384;
    float* gsmT = smemf + 32768;
    float* csm  = gsmT + 1024;

    const int tid = threadIdx.x;
    const int cb  = blockIdx.x * 4;
    const int grp = blockIdx.x >> 4;

    for (int idx = tid; idx < HH * 16; idx += 512) {
        int k = idx >> 4, j = idx & 15;
        float v = R[(size_t)k * G4H + (j >> 2) * HH + cb + (j & 3)];
        Rdup[k * 32 + j * 2]     = v;
        Rdup[k * 32 + j * 2 + 1] = v;
    }
    if (tid < 256)
        __stcg(&d_hT[(cb + (tid >> 6)) * BB + (tid & 63)], 0.f);
    if (tid < 256) csm[tid] = 0.f;
    grid_barrier(grp);

    const int lane = tid & 31;
    const int wi   = tid >> 5;
    const int jg   = lane >> 4;
    const int bg   = lane & 15;

    const ulonglong2* RdU2 = (const ulonglong2*)Rdup;

    const int rj   = tid >> 5;
    const int rbp  = tid & 31;
    const int rb0  = rbp * 2;
    const int rcol = (rj >> 2) * HH + cb + (rj & 3);

    for (int t = 0; t < TT; ++t) {
        const float* hcur = d_hT + (t & 1) * (HH * BB);
        float* hnxt       = d_hT + ((t + 1) & 1) * (HH * BB);
        const float* xkt  = xk + (size_t)t * BB * G4H;

        float xpre0 = __ldg(xkt + (size_t)rb0 * G4H + rcol);
        float xpre1 = __ldg(xkt + (size_t)(rb0 + 1) * G4H + rcol);

        unsigned long long acc2[8][2];
#pragma unroll
        for (int i = 0; i < 8; ++i) { acc2[i][0] = 0ULL; acc2[i][1] = 0ULL; }

        const double2* hp = (const double2*)(hcur + wi * 32 * 64 + bg * 4);
        const ulonglong2* rp = RdU2 + wi * 32 * 8 + jg * 4;
#pragma unroll 8
        for (int kk = 0; kk < 32; ++kk) {
            double2 hd = __ldcg(hp + kk * 16);
            unsigned long long h01 = __double_as_longlong(hd.x);
            unsigned long long h23 = __double_as_longlong(hd.y);
            const ulonglong2* rr = rp + kk * 8;
#pragma unroll
            for (int i = 0; i < 4; ++i) {
                ulonglong2 rv = rr[i];
                FMA2(acc2[2 * i][0],     rv.x, h01);
                FMA2(acc2[2 * i][1],     rv.x, h23);
                FMA2(acc2[2 * i + 1][0], rv.y, h01);
                FMA2(acc2[2 * i + 1][1], rv.y, h23);
            }
        }

        {
            float4* pw4 = (float4*)pw;
#pragma unroll
            for (int ji = 0; ji < 8; ++ji) {
                int j = jg * 8 + ji;
                float4 v;
                v.x = f2lo(acc2[ji][0]); v.y = f2hi(acc2[ji][0]);
                v.z = f2lo(acc2[ji][1]); v.w = f2hi(acc2[ji][1]);
                pw4[wi * 256 + j * 16 + bg] = v;
            }
        }
        __syncthreads();

        {
            const unsigned long long* pw2 = (const unsigned long long*)pw;
            unsigned long long a = pw2[rj * 32 + rbp];
#pragma unroll
            for (int w2 = 1; w2 < 16; ++w2) {
                unsigned long long o = pw2[w2 * 512 + rj * 32 + rbp];
                ADD2PK(a, a, o);
            }
            float g0 = f2lo(a) + xpre0;
            float g1 = f2hi(a) + xpre1;
            ((float2*)gsmT)[rj * 32 + rbp] = make_float2(g0, g1);
        }
        __syncthreads();

        if (tid < 256) {
            int b = tid >> 2, u = tid & 3;
            float iv = gsmT[u * BB + b];
            float fv = gsmT[(4 + u) * BB + b];
            float gv = gsmT[(8 + u) * BB + b];
            float ov = gsmT[(12 + u) * BB + b];
            float c = fsig(fv) * csm[tid] + fsig(iv) * ftanh(gv);
            float h = fsig(ov) * ftanh(c);
            csm[tid] = c;
            __stcg(&hnxt[(cb + u) * BB + b], h);
            hseq[((size_t)t * BB + b) * HH + cb + u] = h;
        }
        grid_barrier(grp);
    }
}

// ------------------------------ LayerNorm ------------------------------------
__global__ __launch_bounds__(128)
void ln_kernel(const float* __restrict__ x, const float* __restrict__ gamma,
               const float* __restrict__ beta, float* __restrict__ y) {
    const int m = blockIdx.x;
    const int tid = threadIdx.x;
    __shared__ float red[4];
    float4 v = *(const float4*)(x + (size_t)m * HH + tid * 4);

    float s = v.x + v.y + v.z + v.w;
#pragma unroll
    for (int o = 16; o; o >>= 1) s += __shfl_down_sync(0xffffffffu, s, o);
    if ((tid & 31) == 0) red[tid >> 5] = s;
    __syncthreads();
    float mu = (red[0] + red[1] + red[2] + red[3]) * (1.f / HH);
    __syncthreads();

    float dx = v.x - mu, dy = v.y - mu, dz = v.z - mu, dw = v.w - mu;
    float s2 = dx * dx + dy * dy + dz * dz + dw * dw;
#pragma unroll
    for (int o = 16; o; o >>= 1) s2 += __shfl_down_sync(0xffffffffu, s2, o);
    if ((tid & 31) == 0) red[tid >> 5] = s2;
    __syncthreads();
    float var = (red[0] + red[1] + red[2] + red[3]) * (1.f / HH);
    float rs = rsqrtf(var + 1e-3f);

    float4 g = *(const float4*)(gamma + tid * 4);
    float4 b = *(const float4*)(beta + tid * 4);
    float4 o4;
    o4.x = dx * rs * g.x + b.x;
    o4.y = dy * rs * g.y + b.y;
    o4.z = dz * rs * g.z + b.z;
    o4.w = dw * rs * g.w + b.w;
    *(float4*)(y + (size_t)m * HH + tid * 4) = o4;
}

// ------------------------------ launch ---------------------------------------
extern "C" void kernel_launch(void* const* d_in, const int* in_sizes, int n_in,
                              void* d_out, int out_size) {
    const float* z     = (const float*)d_in[0];
    const float* Wp    = (const float*)d_in[1];
    const float* bp    = (const float*)d_in[2];
    const float* Ws    = (const float*)d_in[3];
    const float* bs    = (const float*)d_in[4];
    const float* K0    = (const float*)d_in[5];
    const float* R0    = (const float*)d_in[6];
    const float* b0    = (const float*)d_in[7];
    const float* K1    = (const float*)d_in[8];
    const float* R1    = (const float*)d_in[9];
    const float* b1    = (const float*)d_in[10];
    const float* K2    = (const float*)d_in[11];
    const float* R2    = (const float*)d_in[12];
    const float* b2    = (const float*)d_in[13];
    const float* gamma = (const float*)d_in[14];
    const float* beta  = (const float*)d_in[15];
    const float* W1    = (const float*)d_in[16];
    const float* b1d   = (const float*)d_in[17];
    const float* W2    = (const float*)d_in[18];
    const float* b2d   = (const float*)d_in[19];
    float* out = (float*)d_out;

    float *xk, *seqA, *seqB, *res, *W0eff, *b0eff;
    __nv_bfloat16 *Xh, *Xl, *Wh, *Wl;
    cudaGetSymbolAddress((void**)&xk,    d_xk);
    cudaGetSymbolAddress((void**)&seqA,  d_seqA);
    cudaGetSymbolAddress((void**)&seqB,  d_seqB);
    cudaGetSymbolAddress((void**)&res,   d_res);
    cudaGetSymbolAddress((void**)&W0eff, d_W0eff);
    cudaGetSymbolAddress((void**)&b0eff, d_b0eff);
    cudaGetSymbolAddress((void**)&Xh,    d_Xh);
    cudaGetSymbolAddress((void**)&Xl,    d_Xl);
    cudaGetSymbolAddress((void**)&Wh,    d_Wh);
    cudaGetSymbolAddress((void**)&Wl,    d_Wl);

    // idempotent every call (no static guards allowed)
    const int lstm_smem = LSTM_SMEM_FLOATS * 4;  // ~134 KB
    cudaFuncSetAttribute(lstm_kernel,
                         cudaFuncAttributeMaxDynamicSharedMemorySize, lstm_smem);

    const dim3 mma_grid(G4H / 64, MROWS / 128);

    // 1) fold: b0eff = bp@K0 + b0 ; W0eff = Wp@K0
    bias_fold_kernel<<<G4H / 32, 256>>>(bp, K0, b0);
    sgemm64<0,0,0><<<dim3(G4H/64, ZZ/64), 256>>>(Wp, K0, nullptr,
                                                 W0eff, ZZ, G4H, 2*HH);
    // 2) xK0 = z @ W0eff + b0eff   ([t][b] row order)
    sgemm128<1,0,0,1><<<dim3(G4H/128, MROWS/128), 256>>>(z, nullptr, W0eff, b0eff,
                                                         xk, MROWS, G4H, ZZ);
    // 3) LSTM 0 -> seqA
    lstm_kernel<<<LSTM_BLOCKS, 512, lstm_smem>>>(xk, R0, seqA);
    // 4) residual = z @ Ws + bs   ([t][b] row order)
    sgemm128<1,0,0,1><<<dim3(HH/128, MROWS/128), 256>>>(z, nullptr, Ws, bs,
                                                        res, MROWS, HH, ZZ);
    // 5) xK1 = seqA @ K1 + b1   (mma.sync bf16x3)
    convW_kernel<<<(G4H * HH) / 256, 256>>>(K1);
    convA_kernel<0><<<(MROWS * HH) / 256, 256>>>(seqA, nullptr);
    mma_gemm_kernel<<<mma_grid, 256>>>(Xh, Xl, Wh, Wl, b1, xk);
    // 6) LSTM 1 -> seqB
    lstm_kernel<<<LSTM_BLOCKS, 512, lstm_smem>>>(xk, R1, seqB);
    // 7) xK2 = (seqB + res) @ K2 + b2   (mma.sync bf16x3)
    convW_kernel<<<(G4H * HH) / 256, 256>>>(K2);
    convA_kernel<1><<<(MROWS * HH) / 256, 256>>>(seqB, res);
    mma_gemm_kernel<<<mma_grid, 256>>>(Xh, Xl, Wh, Wl, b2, xk);
    // 8) LSTM 2 -> seqA
    lstm_kernel<<<LSTM_BLOCKS, 512, lstm_smem>>>(xk, R2, seqA);
    // 9) LayerNorm: seqA -> seqB
    ln_kernel<<<MROWS, 128>>>(seqA, gamma, beta, seqB);
    // 10) y1 = relu(seqB @ W1 + b1d) -> seqA
    sgemm128<0,1,0,1><<<dim3(HH/128, MROWS/128), 256>>>(seqB, nullptr, W1, b1d,
                                                        seqA, MROWS, HH, HH);
    // 11) out = tanh(seqA @ W2 + b2d) -> d_out  ([b][t] row order)
    sgemm64<2,1,1><<<dim3(FF/64, MROWS/64), 256>>>(seqA, W2, b2d,
                                                   out, MROWS, FF, HH);
}

// round 15
// speedup vs baseline: 1.6468x; 1.0281x over previous
#include <cuda_runtime.h>
#include <cuda_bf16.h>
#include <math.h>

// Problem dims
#define BB 64
#define TT 256
#define ZZ 128
#define HH 512
#define FF 64
#define MROWS (BB*TT)      // 16384
#define G4H   (4*HH)       // 2048
#define LSTM_BLOCKS (HH/4) // 128

// ------------------------------ scratch buffers ------------------------------
__device__ float d_xk[MROWS * G4H];     // 134 MB  gate pre-activations
__device__ float d_seqA[MROWS * HH];
__device__ float d_seqB[MROWS * HH];
__device__ float d_res[MROWS * HH];
__device__ float d_W0eff[ZZ * G4H];
__device__ float d_b0eff[G4H];
__device__ float d_hT[2 * HH * BB];     // double-buffered h
__device__ __nv_bfloat16 d_Xh[MROWS * HH];   // bf16 hi of activations
__device__ __nv_bfloat16 d_Xl[MROWS * HH];   // bf16 lo
__device__ __nv_bfloat16 d_Wh[G4H * HH];     // bf16 hi of W^T [n][k]
__device__ __nv_bfloat16 d_Wl[G4H * HH];     // bf16 lo
__device__ unsigned g_grp[8];
__device__ unsigned g_root;
__device__ unsigned g_gen;

// fast gate nonlinearities (MUFU EX2 path, rel err ~1e-6)
__device__ __forceinline__ float fsig(float x)  { return __fdividef(1.f, 1.f + __expf(-x)); }
__device__ __forceinline__ float ftanh(float x) { return 1.f - __fdividef(2.f, 1.f + __expf(2.f * x)); }

// packed f32x2 helpers (LSTM only)
#define FMA2(c, a, b) \
    asm("fma.rn.f32x2 %0, %2, %3, %1;" : "=l"(c) : "l"(c), "l"(a), "l"(b))
#define ADD2PK(d, a, b) \
    asm("add.rn.f32x2 %0, %1, %2;" : "=l"(d) : "l"(a), "l"(b))

__device__ __forceinline__ float f2lo(unsigned long long v) { return __uint_as_float((unsigned)v); }
__device__ __forceinline__ float f2hi(unsigned long long v) { return __uint_as_float((unsigned)(v >> 32)); }

__device__ __forceinline__ unsigned smem_u32(const void* p) {
    unsigned a;
    asm("{ .reg .u64 t; cvta.to.shared.u64 t, %1; cvt.u32.u64 %0, t; }" : "=r"(a) : "l"(p));
    return a;
}

// ------------------------------ mma.sync helpers (non-'a' ISA, sm_80+) -------
__device__ __forceinline__ void ldsm4(unsigned* r, unsigned addr) {
    asm volatile("ldmatrix.sync.aligned.m8n8.x4.shared.b16 {%0,%1,%2,%3}, [%4];"
                 : "=r"(r[0]), "=r"(r[1]), "=r"(r[2]), "=r"(r[3]) : "r"(addr));
}
__device__ __forceinline__ void mma16816(float* c, const unsigned* a, const unsigned* b) {
    asm volatile(
        "mma.sync.aligned.m16n8k16.row.col.f32.bf16.bf16.f32 "
        "{%0,%1,%2,%3}, {%4,%5,%6,%7}, {%8,%9}, {%0,%1,%2,%3};"
        : "+f"(c[0]), "+f"(c[1]), "+f"(c[2]), "+f"(c[3])
        : "r"(a[0]), "r"(a[1]), "r"(a[2]), "r"(a[3]), "r"(b[0]), "r"(b[1]));
}

// ------------------------------ bf16 conversion kernels ----------------------
// W [Kd][Nd] fp32 -> Wh/Wl [Nd][Kd] bf16 (transposed to K-major). grid = Kd*Nd/256
__global__ void convW_kernel(const float* __restrict__ W, int Kd, int Nd) {
    int id = blockIdx.x * 256 + threadIdx.x;
    int k = id % Kd, n = id / Kd;
    float v = W[(size_t)k * Nd + n];
    __nv_bfloat16 h = __float2bfloat16(v);
    d_Wh[id] = h;
    d_Wl[id] = __float2bfloat16(v - __bfloat162float(h));
}
// X [MROWS][Kd] fp32 -> Xh/Xl bf16. REMAP: out-row m reads A row (m&63)*TT+(m>>6).
template<int REMAP, int ADD2>
__global__ void convA_kernel(const float* __restrict__ A, const float* __restrict__ A2,
                             int Kd) {
    int id = blockIdx.x * 256 + threadIdx.x;
    int m = id / Kd, k = id % Kd;
    int arow = REMAP ? ((m & 63) * TT + (m >> 6)) : m;
    float v = A[(size_t)arow * Kd + k];
    if (ADD2) v += A2[id];
    __nv_bfloat16 h = __float2bfloat16(v);
    d_Xh[id] = h;
    d_Xl[id] = __float2bfloat16(v - __bfloat162float(h));
}

// ------------------------------ bf16x3 mma.sync GEMM -------------------------
// D[MROWS,Nd] = X[MROWS,K] @ W[K,Nd] + bias, fp32 out.  K = KCHUNKS*32.
// Block 128x64, 8 warps (warp tile 32x32), bf16x3 (AhBh+AhBl+AlBh). ACT1=relu.
#define PADK 40   // 32 k + 8 pad -> 80B row stride, conflict-free LDSM
template<int KCHUNKS, int ACT>
__global__ __launch_bounds__(256)
void mma_gemm_kernel(const __nv_bfloat16* __restrict__ Xh,
                     const __nv_bfloat16* __restrict__ Xl,
                     const __nv_bfloat16* __restrict__ Wh,
                     const __nv_bfloat16* __restrict__ Wl,
                     const float* __restrict__ bias,
                     float* __restrict__ out, int Nd) {
    __shared__ __nv_bfloat16 Ah[128 * PADK], Al[128 * PADK];
    __shared__ __nv_bfloat16 Bh[64 * PADK],  Bl[64 * PADK];
    const int Kd = KCHUNKS * 32;
    const int tid = threadIdx.x, lane = tid & 31, wid = tid >> 5;
    const int n0 = blockIdx.x * 64, m0 = blockIdx.y * 128;
    const int wm = (wid & 3) * 32, wn = (wid >> 2) * 32;

    float acc[2][4][4];
#pragma unroll
    for (int mt = 0; mt < 2; ++mt)
#pragma unroll
        for (int nt = 0; nt < 4; ++nt)
#pragma unroll
            for (int i = 0; i < 4; ++i) acc[mt][nt][i] = 0.f;

    const int aRow = lane & 15;
    const int aK   = (lane >> 4) * 8;
    const int bRow = ((lane >> 4) & 1) * 8 + (lane & 7);
    const int bK   = ((lane >> 3) & 1) * 8;
    const unsigned ahb = smem_u32(Ah), alb = smem_u32(Al);
    const unsigned bhb = smem_u32(Bh), blb = smem_u32(Bl);

    const int ldrow = tid >> 2, ldseg = (tid & 3) * 8;

    for (int kc = 0; kc < KCHUNKS; ++kc) {
        const int kg = kc * 32;
#pragma unroll
        for (int i = 0; i < 2; ++i) {
            int row = ldrow + i * 64;
            size_t g = (size_t)(m0 + row) * Kd + kg + ldseg;
            *(uint4*)&Ah[row * PADK + ldseg] = *(const uint4*)(Xh + g);
            *(uint4*)&Al[row * PADK + ldseg] = *(const uint4*)(Xl + g);
        }
        {
            size_t g = (size_t)(n0 + ldrow) * Kd + kg + ldseg;
            *(uint4*)&Bh[ldrow * PADK + ldseg] = *(const uint4*)(Wh + g);
            *(uint4*)&Bl[ldrow * PADK + ldseg] = *(const uint4*)(Wl + g);
        }
        __syncthreads();
#pragma unroll
        for (int q = 0; q < 2; ++q) {
            unsigned fah[2][4], fal[2][4], fbh[2][4], fbl[2][4];
#pragma unroll
            for (int mt = 0; mt < 2; ++mt) {
                unsigned off = (unsigned)(((wm + mt * 16 + aRow) * PADK + q * 16 + aK) * 2);
                ldsm4(fah[mt], ahb + off);
                ldsm4(fal[mt], alb + off);
            }
#pragma unroll
            for (int np = 0; np < 2; ++np) {
                unsigned off = (unsigned)(((wn + np * 16 + bRow) * PADK + q * 16 + bK) * 2);
                ldsm4(fbh[np], bhb + off);
                ldsm4(fbl[np], blb + off);
            }
#pragma unroll
            for (int mt = 0; mt < 2; ++mt)
#pragma unroll
                for (int nt = 0; nt < 4; ++nt) {
                    const unsigned* bh2 = &fbh[nt >> 1][(nt & 1) * 2];
                    const unsigned* bl2 = &fbl[nt >> 1][(nt & 1) * 2];
                    mma16816(acc[mt][nt], fah[mt], bh2);
                    mma16816(acc[mt][nt], fah[mt], bl2);
                    mma16816(acc[mt][nt], fal[mt], bh2);
                }
        }
        __syncthreads();
    }

    const int r = lane >> 2, cp = (lane & 3) * 2;
#pragma unroll
    for (int mt = 0; mt < 2; ++mt) {
        int m_lo = m0 + wm + mt * 16 + r;
        int m_hi = m_lo + 8;
#pragma unroll
        for (int nt = 0; nt < 4; ++nt) {
            int n = n0 + wn + nt * 8 + cp;
            float b0 = bias[n], b1 = bias[n + 1];
            float v00 = acc[mt][nt][0] + b0, v01 = acc[mt][nt][1] + b1;
            float v10 = acc[mt][nt][2] + b0, v11 = acc[mt][nt][3] + b1;
            if (ACT == 1) {
                v00 = fmaxf(v00, 0.f); v01 = fmaxf(v01, 0.f);
                v10 = fmaxf(v10, 0.f); v11 = fmaxf(v11, 0.f);
            }
            *(float2*)(out + (size_t)m_lo * Nd + n) = make_float2(v00, v01);
            *(float2*)(out + (size_t)m_hi * Nd + n) = make_float2(v10, v11);
        }
    }
}

// ------------------------------ hierarchical grid barrier --------------------
__device__ __forceinline__ void grid_barrier(int grp) {
    __syncthreads();
    if (threadIdx.x == 0) {
        __threadfence();
        unsigned my = *(volatile unsigned*)&g_gen;
        if ((atomicAdd(&g_grp[grp], 1u) & 15u) == 15u) {
            if ((atomicAdd(&g_root, 1u) & 7u) == 7u) {
                atomicAdd(&g_gen, 1u);
            }
        }
        while (*(volatile unsigned*)&g_gen == my) {}
        __threadfence();
    }
    __syncthreads();
}

// ------------------------------ bias fold ------------------------------------
__global__ void bias_fold_kernel(const float* __restrict__ bp,
                                 const float* __restrict__ K0,
                                 const float* __restrict__ b0) {
    __shared__ float red[8][32];
    const int c = threadIdx.x & 31, s = threadIdx.x >> 5;
    const int j = blockIdx.x * 32 + c;
    float acc = 0.f;
    for (int k = s * 128; k < s * 128 + 128; ++k)
        acc += bp[k] * K0[(size_t)k * G4H + j];
    red[s][c] = acc;
    __syncthreads();
    if (s == 0) {
        float t = 0.f;
#pragma unroll
        for (int r = 0; r < 8; ++r) t += red[r][c];
        d_b0eff[j] = t + b0[j];
    }
}

// ------------------------------ SGEMM 64x64x16 (small shapes) ----------------
template<int ACT, int OMAP, int HASB>
__global__ __launch_bounds__(256)
void sgemm64(const float* __restrict__ A, const float* __restrict__ Bm,
             const float* __restrict__ bias, float* __restrict__ C,
             int M, int N, int K) {
    __shared__ float As[16][64];
    __shared__ float Bs[16][64];
    const int tid = threadIdx.x;
    const int tx = tid & 15, ty = tid >> 4;
    const int n0 = blockIdx.x * 64, m0 = blockIdx.y * 64;

    float acc[4][4];
#pragma unroll
    for (int i = 0; i < 4; ++i)
#pragma unroll
        for (int j = 0; j < 4; ++j) acc[i][j] = 0.f;

    const int arowl = tid >> 2;
    const int kq = (tid & 3) * 4;
    const int krow = tid >> 4;
    const int nq = (tid & 15) * 4;

    for (int k0 = 0; k0 < K; k0 += 16) {
        {
            int m = m0 + arowl;
            float4 av = *(const float4*)(A + (size_t)m * K + k0 + kq);
            As[kq + 0][arowl] = av.x;
            As[kq + 1][arowl] = av.y;
            As[kq + 2][arowl] = av.z;
            As[kq + 3][arowl] = av.w;
        }
        *(float4*)&Bs[krow][nq] =
            *(const float4*)(Bm + (size_t)(k0 + krow) * N + n0 + nq);
        __syncthreads();
#pragma unroll
        for (int k = 0; k < 16; ++k) {
            float4 a = *(const float4*)&As[k][ty * 4];
            float4 b = *(const float4*)&Bs[k][tx * 4];
            float ar[4] = {a.x, a.y, a.z, a.w};
            float br[4] = {b.x, b.y, b.z, b.w};
#pragma unroll
            for (int i = 0; i < 4; ++i)
#pragma unroll
                for (int j = 0; j < 4; ++j) acc[i][j] += ar[i] * br[j];
        }
        __syncthreads();
    }

#pragma unroll
    for (int i = 0; i < 4; ++i) {
        int m = m0 + ty * 4 + i;
        size_t ro = (OMAP == 1) ? (size_t)((m & 63) * TT + (m >> 6)) * N
                                : (size_t)m * N;
        float4 v;
        float* vp = (float*)&v;
#pragma unroll
        for (int j = 0; j < 4; ++j) {
            int n = n0 + tx * 4 + j;
            float t = acc[i][j];
            if (HASB) t += bias[n];
            if (ACT == 2) t = tanhf(t);
            vp[j] = t;
        }
        *(float4*)(C + ro + n0 + tx * 4) = v;
    }
}

// ------------------------------ LSTM recurrence v4 ---------------------------
#define LSTM_SMEM_FLOATS (16384 + 16384 + 1024 + 256)
__global__ __launch_bounds__(512)
void lstm_kernel(const float* __restrict__ xk, const float* __restrict__ R,
                 float* __restrict__ hseq) {
    extern __shared__ float smemf[];
    float* pw   = smemf;
    float* Rdup = smemf + 16384;
    float* gsmT = smemf + 32768;
    float* csm  = gsmT + 1024;

    const int tid = threadIdx.x;
    const int cb  = blockIdx.x * 4;
    const int grp = blockIdx.x >> 4;

    for (int idx = tid; idx < HH * 16; idx += 512) {
        int k = idx >> 4, j = idx & 15;
        float v = R[(size_t)k * G4H + (j >> 2) * HH + cb + (j & 3)];
        Rdup[k * 32 + j * 2]     = v;
        Rdup[k * 32 + j * 2 + 1] = v;
    }
    if (tid < 256)
        __stcg(&d_hT[(cb + (tid >> 6)) * BB + (tid & 63)], 0.f);
    if (tid < 256) csm[tid] = 0.f;
    grid_barrier(grp);

    const int lane = tid & 31;
    const int wi   = tid >> 5;
    const int jg   = lane >> 4;
    const int bg   = lane & 15;

    const ulonglong2* RdU2 = (const ulonglong2*)Rdup;

    const int rj   = tid >> 5;
    const int rbp  = tid & 31;
    const int rb0  = rbp * 2;
    const int rcol = (rj >> 2) * HH + cb + (rj & 3);

    for (int t = 0; t < TT; ++t) {
        const float* hcur = d_hT + (t & 1) * (HH * BB);
        float* hnxt       = d_hT + ((t + 1) & 1) * (HH * BB);
        const float* xkt  = xk + (size_t)t * BB * G4H;

        float xpre0 = __ldg(xkt + (size_t)rb0 * G4H + rcol);
        float xpre1 = __ldg(xkt + (size_t)(rb0 + 1) * G4H + rcol);

        unsigned long long acc2[8][2];
#pragma unroll
        for (int i = 0; i < 8; ++i) { acc2[i][0] = 0ULL; acc2[i][1] = 0ULL; }

        const double2* hp = (const double2*)(hcur + wi * 32 * 64 + bg * 4);
        const ulonglong2* rp = RdU2 + wi * 32 * 8 + jg * 4;
#pragma unroll 8
        for (int kk = 0; kk < 32; ++kk) {
            double2 hd = __ldcg(hp + kk * 16);
            unsigned long long h01 = __double_as_longlong(hd.x);
            unsigned long long h23 = __double_as_longlong(hd.y);
            const ulonglong2* rr = rp + kk * 8;
#pragma unroll
            for (int i = 0; i < 4; ++i) {
                ulonglong2 rv = rr[i];
                FMA2(acc2[2 * i][0],     rv.x, h01);
                FMA2(acc2[2 * i][1],     rv.x, h23);
                FMA2(acc2[2 * i + 1][0], rv.y, h01);
                FMA2(acc2[2 * i + 1][1], rv.y, h23);
            }
        }

        {
            float4* pw4 = (float4*)pw;
#pragma unroll
            for (int ji = 0; ji < 8; ++ji) {
                int j = jg * 8 + ji;
                float4 v;
                v.x = f2lo(acc2[ji][0]); v.y = f2hi(acc2[ji][0]);
                v.z = f2lo(acc2[ji][1]); v.w = f2hi(acc2[ji][1]);
                pw4[wi * 256 + j * 16 + bg] = v;
            }
        }
        __syncthreads();

        {
            const unsigned long long* pw2 = (const unsigned long long*)pw;
            unsigned long long a = pw2[rj * 32 + rbp];
#pragma unroll
            for (int w2 = 1; w2 < 16; ++w2) {
                unsigned long long o = pw2[w2 * 512 + rj * 32 + rbp];
                ADD2PK(a, a, o);
            }
            float g0 = f2lo(a) + xpre0;
            float g1 = f2hi(a) + xpre1;
            ((float2*)gsmT)[rj * 32 + rbp] = make_float2(g0, g1);
        }
        __syncthreads();

        if (tid < 256) {
            int b = tid >> 2, u = tid & 3;
            float iv = gsmT[u * BB + b];
            float fv = gsmT[(4 + u) * BB + b];
            float gv = gsmT[(8 + u) * BB + b];
            float ov = gsmT[(12 + u) * BB + b];
            float c = fsig(fv) * csm[tid] + fsig(iv) * ftanh(gv);
            float h = fsig(ov) * ftanh(c);
            csm[tid] = c;
            __stcg(&hnxt[(cb + u) * BB + b], h);
            hseq[((size_t)t * BB + b) * HH + cb + u] = h;
        }
        grid_barrier(grp);
    }
}

// ------------------------------ LayerNorm ------------------------------------
__global__ __launch_bounds__(128)
void ln_kernel(const float* __restrict__ x, const float* __restrict__ gamma,
               const float* __restrict__ beta, float* __restrict__ y) {
    const int m = blockIdx.x;
    const int tid = threadIdx.x;
    __shared__ float red[4];
    float4 v = *(const float4*)(x + (size_t)m * HH + tid * 4);

    float s = v.x + v.y + v.z + v.w;
#pragma unroll
    for (int o = 16; o; o >>= 1) s += __shfl_down_sync(0xffffffffu, s, o);
    if ((tid & 31) == 0) red[tid >> 5] = s;
    __syncthreads();
    float mu = (red[0] + red[1] + red[2] + red[3]) * (1.f / HH);
    __syncthreads();

    float dx = v.x - mu, dy = v.y - mu, dz = v.z - mu, dw = v.w - mu;
    float s2 = dx * dx + dy * dy + dz * dz + dw * dw;
#pragma unroll
    for (int o = 16; o; o >>= 1) s2 += __shfl_down_sync(0xffffffffu, s2, o);
    if ((tid & 31) == 0) red[tid >> 5] = s2;
    __syncthreads();
    float var = (red[0] + red[1] + red[2] + red[3]) * (1.f / HH);
    float rs = rsqrtf(var + 1e-3f);

    float4 g = *(const float4*)(gamma + tid * 4);
    float4 b = *(const float4*)(beta + tid * 4);
    float4 o4;
    o4.x = dx * rs * g.x + b.x;
    o4.y = dy * rs * g.y + b.y;
    o4.z = dz * rs * g.z + b.z;
    o4.w = dw * rs * g.w + b.w;
    *(float4*)(y + (size_t)m * HH + tid * 4) = o4;
}

// ------------------------------ launch ---------------------------------------
extern "C" void kernel_launch(void* const* d_in, const int* in_sizes, int n_in,
                              void* d_out, int out_size) {
    const float* z     = (const float*)d_in[0];
    const float* Wp    = (const float*)d_in[1];
    const float* bp    = (const float*)d_in[2];
    const float* Ws    = (const float*)d_in[3];
    const float* bs    = (const float*)d_in[4];
    const float* K0    = (const float*)d_in[5];
    const float* R0    = (const float*)d_in[6];
    const float* b0    = (const float*)d_in[7];
    const float* K1    = (const float*)d_in[8];
    const float* R1    = (const float*)d_in[9];
    const float* b1    = (const float*)d_in[10];
    const float* K2    = (const float*)d_in[11];
    const float* R2    = (const float*)d_in[12];
    const float* b2    = (const float*)d_in[13];
    const float* gamma = (const float*)d_in[14];
    const float* beta  = (const float*)d_in[15];
    const float* W1    = (const float*)d_in[16];
    const float* b1d   = (const float*)d_in[17];
    const float* W2    = (const float*)d_in[18];
    const float* b2d   = (const float*)d_in[19];
    float* out = (float*)d_out;

    float *xk, *seqA, *seqB, *res, *W0eff, *b0eff;
    __nv_bfloat16 *Xh, *Xl, *Wh, *Wl;
    cudaGetSymbolAddress((void**)&xk,    d_xk);
    cudaGetSymbolAddress((void**)&seqA,  d_seqA);
    cudaGetSymbolAddress((void**)&seqB,  d_seqB);
    cudaGetSymbolAddress((void**)&res,   d_res);
    cudaGetSymbolAddress((void**)&W0eff, d_W0eff);
    cudaGetSymbolAddress((void**)&b0eff, d_b0eff);
    cudaGetSymbolAddress((void**)&Xh,    d_Xh);
    cudaGetSymbolAddress((void**)&Xl,    d_Xl);
    cudaGetSymbolAddress((void**)&Wh,    d_Wh);
    cudaGetSymbolAddress((void**)&Wl,    d_Wl);

    // idempotent every call (no static guards allowed)
    const int lstm_smem = LSTM_SMEM_FLOATS * 4;  // ~134 KB
    cudaFuncSetAttribute(lstm_kernel,
                         cudaFuncAttributeMaxDynamicSharedMemorySize, lstm_smem);

    // 1) fold: b0eff = bp@K0 + b0 ; W0eff = Wp@K0
    bias_fold_kernel<<<G4H / 32, 256>>>(bp, K0, b0);
    sgemm64<0,0,0><<<dim3(G4H/64, ZZ/64), 256>>>(Wp, K0, nullptr,
                                                 W0eff, ZZ, G4H, 2*HH);
    // 2) xK0 = z @ W0eff + b0eff   (mma.sync bf16x3, K=128)
    convA_kernel<1,0><<<(MROWS * ZZ) / 256, 256>>>(z, nullptr, ZZ);
    convW_kernel<<<(ZZ * G4H) / 256, 256>>>(W0eff, ZZ, G4H);
    mma_gemm_kernel<4,0><<<dim3(G4H/64, MROWS/128), 256>>>(Xh, Xl, Wh, Wl, b0eff, xk, G4H);
    // 4) residual = z @ Ws + bs  (reuses z conversion; weight buffer reused serially)
    convW_kernel<<<(ZZ * HH) / 256, 256>>>(Ws, ZZ, HH);
    mma_gemm_kernel<4,0><<<dim3(HH/64, MROWS/128), 256>>>(Xh, Xl, Wh, Wl, bs, res, HH);
    // 3) LSTM 0 -> seqA
    lstm_kernel<<<LSTM_BLOCKS, 512, lstm_smem>>>(xk, R0, seqA);
    // 5) xK1 = seqA @ K1 + b1   (mma.sync bf16x3, K=512)
    convW_kernel<<<(HH * G4H) / 256, 256>>>(K1, HH, G4H);
    convA_kernel<0,0><<<(MROWS * HH) / 256, 256>>>(seqA, nullptr, HH);
    mma_gemm_kernel<16,0><<<dim3(G4H/64, MROWS/128), 256>>>(Xh, Xl, Wh, Wl, b1, xk, G4H);
    // 6) LSTM 1 -> seqB
    lstm_kernel<<<LSTM_BLOCKS, 512, lstm_smem>>>(xk, R1, seqB);
    // 7) xK2 = (seqB + res) @ K2 + b2   (mma.sync bf16x3)
    convW_kernel<<<(HH * G4H) / 256, 256>>>(K2, HH, G4H);
    convA_kernel<0,1><<<(MROWS * HH) / 256, 256>>>(seqB, res, HH);
    mma_gemm_kernel<16,0><<<dim3(G4H/64, MROWS/128), 256>>>(Xh, Xl, Wh, Wl, b2, xk, G4H);
    // 8) LSTM 2 -> seqA
    lstm_kernel<<<LSTM_BLOCKS, 512, lstm_smem>>>(xk, R2, seqA);
    // 9) LayerNorm: seqA -> seqB
    ln_kernel<<<MROWS, 128>>>(seqA, gamma, beta, seqB);
    // 10) y1 = relu(seqB @ W1 + b1d) -> seqA  (mma.sync bf16x3, relu)
    convW_kernel<<<(HH * HH) / 256, 256>>>(W1, HH, HH);
    convA_kernel<0,0><<<(MROWS * HH) / 256, 256>>>(seqB, nullptr, HH);
    mma_gemm_kernel<16,1><<<dim3(HH/64, MROWS/128), 256>>>(Xh, Xl, Wh, Wl, b1d, seqA, HH);
    // 11) out = tanh(seqA @ W2 + b2d) -> d_out  ([b][t] row order)
    sgemm64<2,1,1><<<dim3(FF/64, MROWS/64), 256>>>(seqA, W2, b2d,
                                                   out, MROWS, FF, HH);
}